// round 5
// baseline (speedup 1.0000x reference)
#include <cuda_runtime.h>
#include <math.h>

// Persistent single-wave kernel: grid = 148 SMs * 6 blocks = 888 blocks.
// Per block: thread 0 builds the 4x4 SE3 exp-map matrix once into shared
// memory, one __syncthreads, then every thread grid-strides over float4
// columns with no further barriers or wave transitions.
//
// x and out are [4, N] row-major; processed as float4 columns (n4 = N/4).
// Loads .cg (no L1 allocate, zero reuse), stores .cs.
__global__ void __launch_bounds__(256, 6)
se3_persistent(const float4* __restrict__ x, float4* __restrict__ out,
               const float* __restrict__ w, const float* __restrict__ v,
               const float* __restrict__ theta_p, int n4) {
    __shared__ float4 sM[3];

    if (threadIdx.x == 0) {
        const float wx = w[0], wy = w[1], wz = w[2];
        const float vx = v[0], vy = v[1], vz = v[2];
        const float th = theta_p[0];
        const float s = sinf(th);
        const float c = cosf(th);
        const float a = 1.0f - c;      // matches jax fp32: (1 - cos)
        const float b = th - s;        // matches jax fp32: (theta - sin)

        float K[3][3] = { {0.f, -wz,  wy},
                          { wz, 0.f, -wx},
                          {-wy,  wx, 0.f} };
        float KK[3][3];
        #pragma unroll
        for (int r = 0; r < 3; r++)
            #pragma unroll
            for (int j = 0; j < 3; j++)
                KK[r][j] = K[r][0]*K[0][j] + K[r][1]*K[1][j] + K[r][2]*K[2][j];

        float R[3][3], V[3][3];
        #pragma unroll
        for (int r = 0; r < 3; r++)
            #pragma unroll
            for (int j = 0; j < 3; j++) {
                const float I = (r == j) ? 1.0f : 0.0f;
                R[r][j] = I + s * K[r][j] + a * KK[r][j];
                V[r][j] = I * th + a * K[r][j] + b * KK[r][j];
            }

        float t0 = V[0][0]*vx + V[0][1]*vy + V[0][2]*vz;
        float t1 = V[1][0]*vx + V[1][1]*vy + V[1][2]*vz;
        float t2 = V[2][0]*vx + V[2][1]*vy + V[2][2]*vz;

        sM[0] = make_float4(R[0][0], R[0][1], R[0][2], t0);
        sM[1] = make_float4(R[1][0], R[1][1], R[1][2], t1);
        sM[2] = make_float4(R[2][0], R[2][1], R[2][2], t2);
    }
    __syncthreads();

    const float4 m0 = sM[0];
    const float4 m1 = sM[1];
    const float4 m2 = sM[2];

    const size_t s1     = (size_t)n4;
    const size_t stride = (size_t)gridDim.x * blockDim.x;

    for (size_t i = (size_t)blockIdx.x * blockDim.x + threadIdx.x;
         i < s1; i += stride) {
        // Front-batch 4 independent 128-bit loads.
        const float4 x0 = __ldcg(&x[i]);
        const float4 x1 = __ldcg(&x[i + s1]);
        const float4 x2 = __ldcg(&x[i + 2*s1]);
        const float4 x3 = __ldcg(&x[i + 3*s1]);

        float4 r0, r1, r2;
        r0.x = m0.x*x0.x + m0.y*x1.x + m0.z*x2.x + m0.w*x3.x;
        r0.y = m0.x*x0.y + m0.y*x1.y + m0.z*x2.y + m0.w*x3.y;
        r0.z = m0.x*x0.z + m0.y*x1.z + m0.z*x2.z + m0.w*x3.z;
        r0.w = m0.x*x0.w + m0.y*x1.w + m0.z*x2.w + m0.w*x3.w;

        r1.x = m1.x*x0.x + m1.y*x1.x + m1.z*x2.x + m1.w*x3.x;
        r1.y = m1.x*x0.y + m1.y*x1.y + m1.z*x2.y + m1.w*x3.y;
        r1.z = m1.x*x0.z + m1.y*x1.z + m1.z*x2.z + m1.w*x3.z;
        r1.w = m1.x*x0.w + m1.y*x1.w + m1.z*x2.w + m1.w*x3.w;

        r2.x = m2.x*x0.x + m2.y*x1.x + m2.z*x2.x + m2.w*x3.x;
        r2.y = m2.x*x0.y + m2.y*x1.y + m2.z*x2.y + m2.w*x3.y;
        r2.z = m2.x*x0.z + m2.y*x1.z + m2.z*x2.z + m2.w*x3.z;
        r2.w = m2.x*x0.w + m2.y*x1.w + m2.z*x2.w + m2.w*x3.w;

        __stcs(&out[i],        r0);
        __stcs(&out[i + s1],   r1);
        __stcs(&out[i + 2*s1], r2);
        __stcs(&out[i + 3*s1], x3);   // bottom row of M is [0,0,0,1]
    }
}

extern "C" void kernel_launch(void* const* d_in, const int* in_sizes, int n_in,
                              void* d_out, int out_size) {
    const float* x     = (const float*)d_in[0];   // [4, N]
    const float* w     = (const float*)d_in[1];   // [3]
    const float* v     = (const float*)d_in[2];   // [3]
    const float* theta = (const float*)d_in[3];   // scalar

    const int N  = in_sizes[0] / 4;   // columns
    const int n4 = N / 4;             // float4 columns per row

    // One wave: 152 SMs on GB300, 6 blocks/SM at 256 threads (launch_bounds).
    const int threads = 256;
    const int blocks  = 152 * 6;
    se3_persistent<<<blocks, threads>>>((const float4*)x, (float4*)d_out,
                                        w, v, theta, n4);
}

// round 6
// speedup vs baseline: 1.1230x; 1.1230x over previous
#include <cuda_runtime.h>
#include <math.h>

// One-shot fused kernel using sm_10x 256-bit global loads/stores.
// Each thread handles 8 consecutive columns (one v8 chunk) of each of the
// 4 rows of x [4, N] row-major. Per block: thread 0 builds the SE3 matrix
// into shared memory (overlapped with the front-batched loads), one barrier,
// then FMAs + 256-bit stores. Row 3 of M is [0,0,0,1] -> out row3 = x row3.

__device__ __forceinline__ void ldg256(const float* __restrict__ p, float r[8]) {
    asm volatile("ld.global.nc.v8.f32 {%0,%1,%2,%3,%4,%5,%6,%7}, [%8];"
                 : "=f"(r[0]), "=f"(r[1]), "=f"(r[2]), "=f"(r[3]),
                   "=f"(r[4]), "=f"(r[5]), "=f"(r[6]), "=f"(r[7])
                 : "l"(p));
}

__device__ __forceinline__ void stg256(float* p, const float r[8]) {
    asm volatile("st.global.v8.f32 [%0], {%1,%2,%3,%4,%5,%6,%7,%8};"
                 :: "l"(p),
                    "f"(r[0]), "f"(r[1]), "f"(r[2]), "f"(r[3]),
                    "f"(r[4]), "f"(r[5]), "f"(r[6]), "f"(r[7])
                 : "memory");
}

__global__ void __launch_bounds__(256, 4)
se3_fused_v8(const float* __restrict__ x, float* __restrict__ out,
             const float* __restrict__ w, const float* __restrict__ v,
             const float* __restrict__ theta_p, int n8 /* N/8 */, int rowN) {
    __shared__ float4 sM[3];

    const int i = blockIdx.x * blockDim.x + threadIdx.x;
    const bool active = (i < n8);
    const size_t base = (size_t)i * 8;
    const size_t s1   = (size_t)rowN;

    // ---- 1. front-batch 4 x 256-bit loads (independent of M) ----
    float x0[8], x1[8], x2[8], x3[8];
    if (active) {
        ldg256(x + base,        x0);
        ldg256(x + base + s1,   x1);
        ldg256(x + base + 2*s1, x2);
        ldg256(x + base + 3*s1, x3);
    }

    // ---- 2. matrix build (thread 0 only), overlapped with loads ----
    if (threadIdx.x == 0) {
        const float wx = w[0], wy = w[1], wz = w[2];
        const float vx = v[0], vy = v[1], vz = v[2];
        const float th = theta_p[0];
        const float s = sinf(th);
        const float c = cosf(th);
        const float a = 1.0f - c;      // matches jax fp32: (1 - cos)
        const float b = th - s;        // matches jax fp32: (theta - sin)

        float K[3][3] = { {0.f, -wz,  wy},
                          { wz, 0.f, -wx},
                          {-wy,  wx, 0.f} };
        float KK[3][3];
        #pragma unroll
        for (int r = 0; r < 3; r++)
            #pragma unroll
            for (int j = 0; j < 3; j++)
                KK[r][j] = K[r][0]*K[0][j] + K[r][1]*K[1][j] + K[r][2]*K[2][j];

        float R[3][3], V[3][3];
        #pragma unroll
        for (int r = 0; r < 3; r++)
            #pragma unroll
            for (int j = 0; j < 3; j++) {
                const float I = (r == j) ? 1.0f : 0.0f;
                R[r][j] = I + s * K[r][j] + a * KK[r][j];
                V[r][j] = I * th + a * K[r][j] + b * KK[r][j];
            }

        float t0 = V[0][0]*vx + V[0][1]*vy + V[0][2]*vz;
        float t1 = V[1][0]*vx + V[1][1]*vy + V[1][2]*vz;
        float t2 = V[2][0]*vx + V[2][1]*vy + V[2][2]*vz;

        sM[0] = make_float4(R[0][0], R[0][1], R[0][2], t0);
        sM[1] = make_float4(R[1][0], R[1][1], R[1][2], t1);
        sM[2] = make_float4(R[2][0], R[2][1], R[2][2], t2);
    }
    __syncthreads();

    if (!active) return;

    const float4 m0 = sM[0];
    const float4 m1 = sM[1];
    const float4 m2 = sM[2];

    // ---- 3. transform + 256-bit stores, one output row at a time ----
    float r[8];

    #pragma unroll
    for (int e = 0; e < 8; e++)
        r[e] = m0.x*x0[e] + m0.y*x1[e] + m0.z*x2[e] + m0.w*x3[e];
    stg256(out + base, r);

    #pragma unroll
    for (int e = 0; e < 8; e++)
        r[e] = m1.x*x0[e] + m1.y*x1[e] + m1.z*x2[e] + m1.w*x3[e];
    stg256(out + base + s1, r);

    #pragma unroll
    for (int e = 0; e < 8; e++)
        r[e] = m2.x*x0[e] + m2.y*x1[e] + m2.z*x2[e] + m2.w*x3[e];
    stg256(out + base + 2*s1, r);

    stg256(out + base + 3*s1, x3);   // bottom row of M is [0,0,0,1]
}

extern "C" void kernel_launch(void* const* d_in, const int* in_sizes, int n_in,
                              void* d_out, int out_size) {
    const float* x     = (const float*)d_in[0];   // [4, N]
    const float* w     = (const float*)d_in[1];   // [3]
    const float* v     = (const float*)d_in[2];   // [3]
    const float* theta = (const float*)d_in[3];   // scalar

    const int N  = in_sizes[0] / 4;   // columns per row
    const int n8 = N / 8;             // v8 chunks per row

    const int threads = 256;
    const int blocks  = (n8 + threads - 1) / threads;
    se3_fused_v8<<<blocks, threads>>>(x, (float*)d_out, w, v, theta, n8, N);
}

// round 7
// speedup vs baseline: 1.1271x; 1.0037x over previous
#include <cuda_runtime.h>
#include <math.h>

// One-shot fused kernel (best measured shape: 1 float4 column per thread,
// 4 front-batched LDG.128.cg, STG.128.cs, 40 regs, 6 blocks/SM).
// Grid exactly covers n4 (n4 = N/4 is a multiple of 256 for N=16M), so no
// bounds guard: loads are issued unconditionally at kernel start and overlap
// with the per-block matrix build.
//
// x and out are [4, N] row-major; processed as float4 columns (n4 = N/4).
// Row 3 of M is [0,0,0,1] -> out row3 = x row3.
__global__ void __launch_bounds__(256, 6)
se3_fused(const float4* __restrict__ x, float4* __restrict__ out,
          const float* __restrict__ w, const float* __restrict__ v,
          const float* __restrict__ theta_p, int n4) {
    __shared__ float4 sM[3];

    const unsigned i = blockIdx.x * blockDim.x + threadIdx.x;
    const size_t s1 = (size_t)n4;

    // ---- 1. front-batch the 4 streaming loads (independent of M) ----
    const float4 x0 = __ldcg(&x[i]);
    const float4 x1 = __ldcg(&x[i + s1]);
    const float4 x2 = __ldcg(&x[i + 2*s1]);
    const float4 x3 = __ldcg(&x[i + 3*s1]);

    // ---- 2. matrix build (thread 0 only), overlapped with the loads ----
    if (threadIdx.x == 0) {
        const float wx = w[0], wy = w[1], wz = w[2];
        const float vx = v[0], vy = v[1], vz = v[2];
        const float th = theta_p[0];
        const float s = sinf(th);
        const float c = cosf(th);
        const float a = 1.0f - c;      // matches jax fp32: (1 - cos)
        const float b = th - s;        // matches jax fp32: (theta - sin)

        float K[3][3] = { {0.f, -wz,  wy},
                          { wz, 0.f, -wx},
                          {-wy,  wx, 0.f} };
        float KK[3][3];
        #pragma unroll
        for (int r = 0; r < 3; r++)
            #pragma unroll
            for (int j = 0; j < 3; j++)
                KK[r][j] = K[r][0]*K[0][j] + K[r][1]*K[1][j] + K[r][2]*K[2][j];

        float R[3][3], V[3][3];
        #pragma unroll
        for (int r = 0; r < 3; r++)
            #pragma unroll
            for (int j = 0; j < 3; j++) {
                const float I = (r == j) ? 1.0f : 0.0f;
                R[r][j] = I + s * K[r][j] + a * KK[r][j];
                V[r][j] = I * th + a * K[r][j] + b * KK[r][j];
            }

        float t0 = V[0][0]*vx + V[0][1]*vy + V[0][2]*vz;
        float t1 = V[1][0]*vx + V[1][1]*vy + V[1][2]*vz;
        float t2 = V[2][0]*vx + V[2][1]*vy + V[2][2]*vz;

        sM[0] = make_float4(R[0][0], R[0][1], R[0][2], t0);
        sM[1] = make_float4(R[1][0], R[1][1], R[1][2], t1);
        sM[2] = make_float4(R[2][0], R[2][1], R[2][2], t2);
    }
    __syncthreads();

    // ---- 3. transform + store ----
    const float4 m0 = sM[0];
    const float4 m1 = sM[1];
    const float4 m2 = sM[2];

    float4 r0, r1, r2;
    r0.x = m0.x*x0.x + m0.y*x1.x + m0.z*x2.x + m0.w*x3.x;
    r0.y = m0.x*x0.y + m0.y*x1.y + m0.z*x2.y + m0.w*x3.y;
    r0.z = m0.x*x0.z + m0.y*x1.z + m0.z*x2.z + m0.w*x3.z;
    r0.w = m0.x*x0.w + m0.y*x1.w + m0.z*x2.w + m0.w*x3.w;

    r1.x = m1.x*x0.x + m1.y*x1.x + m1.z*x2.x + m1.w*x3.x;
    r1.y = m1.x*x0.y + m1.y*x1.y + m1.z*x2.y + m1.w*x3.y;
    r1.z = m1.x*x0.z + m1.y*x1.z + m1.z*x2.z + m1.w*x3.z;
    r1.w = m1.x*x0.w + m1.y*x1.w + m1.z*x2.w + m1.w*x3.w;

    r2.x = m2.x*x0.x + m2.y*x1.x + m2.z*x2.x + m2.w*x3.x;
    r2.y = m2.x*x0.y + m2.y*x1.y + m2.z*x2.y + m2.w*x3.y;
    r2.z = m2.x*x0.z + m2.y*x1.z + m2.z*x2.z + m2.w*x3.z;
    r2.w = m2.x*x0.w + m2.y*x1.w + m2.z*x2.w + m2.w*x3.w;

    __stcs(&out[i],        r0);
    __stcs(&out[i + s1],   r1);
    __stcs(&out[i + 2*s1], r2);
    __stcs(&out[i + 3*s1], x3);   // bottom row of M is [0,0,0,1]
}

// Fallback with bounds guard for sizes that don't divide evenly.
__global__ void __launch_bounds__(256, 6)
se3_fused_guard(const float4* __restrict__ x, float4* __restrict__ out,
                const float* __restrict__ w, const float* __restrict__ v,
                const float* __restrict__ theta_p, int n4) {
    __shared__ float4 sM[3];

    const unsigned i = blockIdx.x * blockDim.x + threadIdx.x;
    const bool active = (i < (unsigned)n4);
    const size_t s1 = (size_t)n4;

    float4 x0, x1, x2, x3;
    if (active) {
        x0 = __ldcg(&x[i]);
        x1 = __ldcg(&x[i + s1]);
        x2 = __ldcg(&x[i + 2*s1]);
        x3 = __ldcg(&x[i + 3*s1]);
    }

    if (threadIdx.x == 0) {
        const float wx = w[0], wy = w[1], wz = w[2];
        const float vx = v[0], vy = v[1], vz = v[2];
        const float th = theta_p[0];
        const float s = sinf(th);
        const float c = cosf(th);
        const float a = 1.0f - c;
        const float b = th - s;

        float K[3][3] = { {0.f, -wz,  wy},
                          { wz, 0.f, -wx},
                          {-wy,  wx, 0.f} };
        float KK[3][3];
        #pragma unroll
        for (int r = 0; r < 3; r++)
            #pragma unroll
            for (int j = 0; j < 3; j++)
                KK[r][j] = K[r][0]*K[0][j] + K[r][1]*K[1][j] + K[r][2]*K[2][j];

        float R[3][3], V[3][3];
        #pragma unroll
        for (int r = 0; r < 3; r++)
            #pragma unroll
            for (int j = 0; j < 3; j++) {
                const float I = (r == j) ? 1.0f : 0.0f;
                R[r][j] = I + s * K[r][j] + a * KK[r][j];
                V[r][j] = I * th + a * K[r][j] + b * KK[r][j];
            }

        float t0 = V[0][0]*vx + V[0][1]*vy + V[0][2]*vz;
        float t1 = V[1][0]*vx + V[1][1]*vy + V[1][2]*vz;
        float t2 = V[2][0]*vx + V[2][1]*vy + V[2][2]*vz;

        sM[0] = make_float4(R[0][0], R[0][1], R[0][2], t0);
        sM[1] = make_float4(R[1][0], R[1][1], R[1][2], t1);
        sM[2] = make_float4(R[2][0], R[2][1], R[2][2], t2);
    }
    __syncthreads();

    if (!active) return;

    const float4 m0 = sM[0];
    const float4 m1 = sM[1];
    const float4 m2 = sM[2];

    float4 r0, r1, r2;
    r0.x = m0.x*x0.x + m0.y*x1.x + m0.z*x2.x + m0.w*x3.x;
    r0.y = m0.x*x0.y + m0.y*x1.y + m0.z*x2.y + m0.w*x3.y;
    r0.z = m0.x*x0.z + m0.y*x1.z + m0.z*x2.z + m0.w*x3.z;
    r0.w = m0.x*x0.w + m0.y*x1.w + m0.z*x2.w + m0.w*x3.w;

    r1.x = m1.x*x0.x + m1.y*x1.x + m1.z*x2.x + m1.w*x3.x;
    r1.y = m1.x*x0.y + m1.y*x1.y + m1.z*x2.y + m1.w*x3.y;
    r1.z = m1.x*x0.z + m1.y*x1.z + m1.z*x2.z + m1.w*x3.z;
    r1.w = m1.x*x0.w + m1.y*x1.w + m1.z*x2.w + m1.w*x3.w;

    r2.x = m2.x*x0.x + m2.y*x1.x + m2.z*x2.x + m2.w*x3.x;
    r2.y = m2.x*x0.y + m2.y*x1.y + m2.z*x2.y + m2.w*x3.y;
    r2.z = m2.x*x0.z + m2.y*x1.z + m2.z*x2.z + m2.w*x3.z;
    r2.w = m2.x*x0.w + m2.y*x1.w + m2.z*x2.w + m2.w*x3.w;

    __stcs(&out[i],        r0);
    __stcs(&out[i + s1],   r1);
    __stcs(&out[i + 2*s1], r2);
    __stcs(&out[i + 3*s1], x3);
}

extern "C" void kernel_launch(void* const* d_in, const int* in_sizes, int n_in,
                              void* d_out, int out_size) {
    const float* x     = (const float*)d_in[0];   // [4, N]
    const float* w     = (const float*)d_in[1];   // [3]
    const float* v     = (const float*)d_in[2];   // [3]
    const float* theta = (const float*)d_in[3];   // scalar

    const int N  = in_sizes[0] / 4;   // columns
    const int n4 = N / 4;             // float4 columns per row

    const int threads = 256;
    if (n4 % threads == 0) {
        se3_fused<<<n4 / threads, threads>>>((const float4*)x, (float4*)d_out,
                                             w, v, theta, n4);
    } else {
        const int blocks = (n4 + threads - 1) / threads;
        se3_fused_guard<<<blocks, threads>>>((const float4*)x, (float4*)d_out,
                                             w, v, theta, n4);
    }
}